// round 16
// baseline (speedup 1.0000x reference)
#include <cuda_runtime.h>
#include <cuda_fp16.h>
#include <cstdint>

#define OUTF 4096
#define INF  4096
#define MDIM 1024

// scratch — static device globals (allocation-free)
__device__ __half g_xh[(size_t)MDIM * INF];   // x in fp16 [m, k]
__device__ uint2  g_cz[OUTF * 32];            // per (o,g): (-(1032+z) h2, s h2)

// ---------------------------------------------------------------------------
// helpers
// ---------------------------------------------------------------------------
__device__ __forceinline__ uint32_t smem_u32(const void* p) {
    uint32_t a;
    asm("{ .reg .u64 t; cvta.to.shared.u64 t, %1; cvt.u32.u64 %0, t; }"
        : "=r"(a) : "l"(p));
    return a;
}

__device__ __forceinline__ void cp16(uint32_t saddr, const void* gaddr) {
    asm volatile("cp.async.cg.shared.global [%0], [%1], 16;"
                 :: "r"(saddr), "l"(gaddr) : "memory");
}

// ---------------------------------------------------------------------------
// Kernel 1: prep — blocks [0,4096): x fp32->fp16 ; [4096,4608): cz table
// ---------------------------------------------------------------------------
__global__ void prep_kernel(const float4* __restrict__ x,
                            const float* __restrict__ ws,
                            const int* __restrict__ wz) {
    int b = blockIdx.x;
    int t = threadIdx.x;
    if (b < 4096) {
        int i = b * 256 + t;              // one float4 per thread
        float4 v = x[i];
        __half2 a = __floats2half2_rn(v.x, v.y);
        __half2 c = __floats2half2_rn(v.z, v.w);
        uint2 u;
        u.x = *reinterpret_cast<uint32_t*>(&a);
        u.y = *reinterpret_cast<uint32_t*>(&c);
        reinterpret_cast<uint2*>(g_xh)[i] = u;
    } else {
        int idx = (b - 4096) * 256 + t;   // 0..131071 = (o,g) pairs, row-major
        float s = ws[idx];
        float z = (float)wz[idx];
        __half hc = __float2half_rn(-(1032.0f + z));   // integer, fp16-exact
        __half hs = __float2half_rn(s);
        __half2 c2 = __halves2half2(hc, hc);
        __half2 s2 = __halves2half2(hs, hs);
        g_cz[idx] = make_uint2(*reinterpret_cast<uint32_t*>(&c2),
                               *reinterpret_cast<uint32_t*>(&s2));
    }
}

// ---------------------------------------------------------------------------
// Kernel 2: fused dequant + mma.sync fp16 GEMM.
// CTA 128x256, 8 warps (2x4, warp tile 64x64), BK=64 halves, 4-stage pipeline.
// A: cp.async from g_xh.  B: LDG packed int4 -> LOP3 dequant -> STS (fused).
// ---------------------------------------------------------------------------
constexpr int BM = 128, BN = 256, BK = 64;
constexpr int NIT = INF / BK;                 // 64
constexpr int TILE_A = BM * 128;              // 16384 B
constexpr int TILE_B = BN * 128;              // 32768 B
constexpr int STG = TILE_A + TILE_B;          // 49152 B
constexpr int SMEM_BYTES = 4 * STG;           // 196608 B
constexpr int NTHR = 256;

__global__ void __launch_bounds__(NTHR, 1) gemm_kernel(
        const int* __restrict__ wp, float* __restrict__ out) {
    extern __shared__ char smem[];
    const uint32_t sb = smem_u32(smem);
    const int tid = threadIdx.x;
    const int wid = tid >> 5;
    const int lid = tid & 31;
    const int wm = wid >> 2;                  // 0..1  (64 M-rows)
    const int wn = wid & 3;                   // 0..3  (64 N-rows)
    const int n0 = blockIdx.x * BN;
    const int m0 = blockIdx.y * BM;

    const char* gA = (const char*)g_xh + (size_t)m0 * (INF * 2);

    // shared per-thread addressing: row-block rowb, 16B-chunk cc
    const int rowb = tid >> 3;                // 0..31
    const int cc   = tid & 7;
    const uint32_t soff0 = (uint32_t)(rowb * 128 + ((cc ^ (rowb & 7)) << 4));
    const size_t   goffa0 = (size_t)rowb * (INF * 2) + (size_t)cc * 16;
    const int pb0  = ((n0 + rowb) << 9) + cc; // packed-int index base
    const int czb0 = (n0 + rowb) * 32;        // cz table base

    uint2 cz[8];
    uint32_t pk[8];

    auto loadA = [&](int kc) {
        uint32_t tb = sb + (kc & 3) * STG;
#pragma unroll
        for (int r = 0; r < 4; ++r)
            cp16(tb + soff0 + r * 4096, gA + goffa0 + (size_t)r * 262144
                                           + (size_t)kc * 128);
        asm volatile("cp.async.commit_group;" ::: "memory");
    };
    auto loadB = [&](int kc) {
        if ((kc & 1) == 0) {                  // new group (group = 2 chunks)
            int g = kc >> 1;
#pragma unroll
            for (int r = 0; r < 8; ++r) cz[r] = g_cz[czb0 + r * 1024 + g];
        }
#pragma unroll
        for (int r = 0; r < 8; ++r)
            pk[r] = (uint32_t)__ldg(wp + pb0 + r * 16384 + kc * 8);
    };
    auto storeB = [&](int kc) {
        uint32_t tb = sb + (kc & 3) * STG + TILE_A;
#pragma unroll
        for (int r = 0; r < 8; ++r) {
            uint32_t v = pk[r] ^ 0x88888888u;             // signed-nibble bias
            uint32_t u0 = ((v & 0xFu) | ((v & 0xF0u) << 12)) | 0x64006400u;
            uint32_t w1 = v >> 8;
            uint32_t u1 = ((w1 & 0xFu) | ((w1 & 0xF0u) << 12)) | 0x64006400u;
            uint32_t w2 = v >> 16;
            uint32_t u2 = ((w2 & 0xFu) | ((w2 & 0xF0u) << 12)) | 0x64006400u;
            uint32_t w3 = v >> 24;
            uint32_t u3 = ((w3 & 0xFu) | ((w3 & 0xF0u) << 12)) | 0x64006400u;
            __half2 nc = *reinterpret_cast<__half2*>(&cz[r].x);
            __half2 sh = *reinterpret_cast<__half2*>(&cz[r].y);
            __half2 h0 = __hmul2(__hadd2(*reinterpret_cast<__half2*>(&u0), nc), sh);
            __half2 h1 = __hmul2(__hadd2(*reinterpret_cast<__half2*>(&u1), nc), sh);
            __half2 h2 = __hmul2(__hadd2(*reinterpret_cast<__half2*>(&u2), nc), sh);
            __half2 h3 = __hmul2(__hadd2(*reinterpret_cast<__half2*>(&u3), nc), sh);
            asm volatile("st.shared.v4.b32 [%0], {%1, %2, %3, %4};"
                         :: "r"(tb + soff0 + r * 4096),
                            "r"(*reinterpret_cast<uint32_t*>(&h0)),
                            "r"(*reinterpret_cast<uint32_t*>(&h1)),
                            "r"(*reinterpret_cast<uint32_t*>(&h2)),
                            "r"(*reinterpret_cast<uint32_t*>(&h3))
                         : "memory");
        }
    };

    // ldmatrix addressing (mapping validated R3-R13)
    const int a_row7 = wm * 64 + (lid & 15);       // + i*16
    const int a_cb   = lid >> 4;
    const int b_lrow = (lid & 7) + ((lid >> 4) << 3);
    const int b_cb   = (lid >> 3) & 1;
    const int b_row0 = wn * 64 + b_lrow;           // + h*16

    float acc[4][8][4];
#pragma unroll
    for (int i = 0; i < 4; ++i)
#pragma unroll
        for (int j = 0; j < 8; ++j)
#pragma unroll
            for (int q = 0; q < 4; ++q) acc[i][j][q] = 0.f;

    // prologue: chunks 0..2
#pragma unroll
    for (int kc = 0; kc < 3; ++kc) {
        loadA(kc);
        loadB(kc);
        storeB(kc);
    }
    asm volatile("cp.async.wait_group 2;" ::: "memory");
    __syncthreads();

    for (int it = 0; it < NIT; ++it) {
        const uint32_t tb = sb + (it & 3) * STG;
        const bool more = (it + 3 < NIT);
        if (more) {                   // issue loads early; dequant after MMA
            loadA(it + 3);
            loadB(it + 3);
        }

#pragma unroll
        for (int ks = 0; ks < 4; ++ks) {           // 4 x k16 per 64-half chunk
            uint32_t a[4][4];
#pragma unroll
            for (int i = 0; i < 4; ++i) {
                int row = a_row7 + i * 16;
                uint32_t ad = tb + row * 128
                            + ((((ks << 1) + a_cb) ^ (row & 7)) << 4);
                asm volatile(
                    "ldmatrix.sync.aligned.m8n8.x4.shared.b16 {%0,%1,%2,%3}, [%4];"
                    : "=r"(a[i][0]), "=r"(a[i][1]), "=r"(a[i][2]), "=r"(a[i][3])
                    : "r"(ad));
            }
            uint32_t bfr[8][2];
#pragma unroll
            for (int h = 0; h < 4; ++h) {
                int row = b_row0 + h * 16;
                uint32_t bd = tb + TILE_A + row * 128
                            + ((((ks << 1) + b_cb) ^ (row & 7)) << 4);
                uint32_t r0, r1, r2, r3;
                asm volatile(
                    "ldmatrix.sync.aligned.m8n8.x4.shared.b16 {%0,%1,%2,%3}, [%4];"
                    : "=r"(r0), "=r"(r1), "=r"(r2), "=r"(r3) : "r"(bd));
                bfr[2 * h][0] = r0;     bfr[2 * h][1] = r1;
                bfr[2 * h + 1][0] = r2; bfr[2 * h + 1][1] = r3;
            }
#pragma unroll
            for (int i = 0; i < 4; ++i)
#pragma unroll
                for (int j = 0; j < 8; ++j)
                    asm volatile(
                        "mma.sync.aligned.m16n8k16.row.col.f32.f16.f16.f32 "
                        "{%0,%1,%2,%3},{%4,%5,%6,%7},{%8,%9},{%0,%1,%2,%3};"
                        : "+f"(acc[i][j][0]), "+f"(acc[i][j][1]),
                          "+f"(acc[i][j][2]), "+f"(acc[i][j][3])
                        : "r"(a[i][0]), "r"(a[i][1]), "r"(a[i][2]), "r"(a[i][3]),
                          "r"(bfr[j][0]), "r"(bfr[j][1]));
        }

        if (more) {
            storeB(it + 3);           // data arrived during MMA phase
            asm volatile("cp.async.wait_group 2;" ::: "memory");
        } else {
            asm volatile("cp.async.wait_group 0;" ::: "memory");
        }
        __syncthreads();
    }

    // epilogue
    const int mrow = m0 + wm * 64 + (lid >> 2);
    const int ncol = n0 + wn * 64 + ((lid & 3) << 1);
#pragma unroll
    for (int i = 0; i < 4; ++i) {
#pragma unroll
        for (int j = 0; j < 8; ++j) {
            float* p0 = out + (size_t)(mrow + i * 16) * OUTF + ncol + j * 8;
            float* p1 = out + (size_t)(mrow + i * 16 + 8) * OUTF + ncol + j * 8;
            *reinterpret_cast<float2*>(p0) = make_float2(acc[i][j][0], acc[i][j][1]);
            *reinterpret_cast<float2*>(p1) = make_float2(acc[i][j][2], acc[i][j][3]);
        }
    }
}

// ---------------------------------------------------------------------------
// launch
// ---------------------------------------------------------------------------
extern "C" void kernel_launch(void* const* d_in, const int* in_sizes, int n_in,
                              void* d_out, int out_size) {
    const float* x  = (const float*)d_in[0];
    const int*   wp = (const int*)d_in[1];
    const float* ws = (const float*)d_in[2];
    const int*   wz = (const int*)d_in[3];
    float* out = (float*)d_out;

    cudaFuncSetAttribute(gemm_kernel,
                         cudaFuncAttributeMaxDynamicSharedMemorySize, SMEM_BYTES);

    prep_kernel<<<4096 + 512, 256>>>(reinterpret_cast<const float4*>(x), ws, wz);
    gemm_kernel<<<dim3(OUTF / BN, MDIM / BM), NTHR, SMEM_BYTES>>>(wp, out);
}

// round 17
// speedup vs baseline: 1.0081x; 1.0081x over previous
#include <cuda_runtime.h>
#include <cuda_fp16.h>
#include <cstdint>

#define OUTF 4096
#define INF  4096
#define MDIM 1024

// scratch — static device globals (allocation-free)
__device__ __half g_xh[(size_t)MDIM * INF];   // x in fp16 [m, k]
__device__ uint2  g_cz[OUTF * 32];            // per (o,g): (-(1032+z) h2, s h2)

// ---------------------------------------------------------------------------
// helpers
// ---------------------------------------------------------------------------
__device__ __forceinline__ uint32_t smem_u32(const void* p) {
    uint32_t a;
    asm("{ .reg .u64 t; cvta.to.shared.u64 t, %1; cvt.u32.u64 %0, t; }"
        : "=r"(a) : "l"(p));
    return a;
}

__device__ __forceinline__ void cp16(uint32_t saddr, const void* gaddr) {
    asm volatile("cp.async.cg.shared.global [%0], [%1], 16;"
                 :: "r"(saddr), "l"(gaddr) : "memory");
}

// ---------------------------------------------------------------------------
// Kernel 1: prep — blocks [0,4096): x fp32->fp16 ; [4096,4608): cz table
// ---------------------------------------------------------------------------
__global__ void prep_kernel(const float4* __restrict__ x,
                            const float* __restrict__ ws,
                            const int* __restrict__ wz) {
    int b = blockIdx.x;
    int t = threadIdx.x;
    if (b < 4096) {
        int i = b * 256 + t;              // one float4 per thread
        float4 v = x[i];
        __half2 a = __floats2half2_rn(v.x, v.y);
        __half2 c = __floats2half2_rn(v.z, v.w);
        uint2 u;
        u.x = *reinterpret_cast<uint32_t*>(&a);
        u.y = *reinterpret_cast<uint32_t*>(&c);
        reinterpret_cast<uint2*>(g_xh)[i] = u;
    } else {
        int idx = (b - 4096) * 256 + t;   // 0..131071 = (o,g) pairs, row-major
        float s = ws[idx];
        float z = (float)wz[idx];
        __half hc = __float2half_rn(-(1032.0f + z));   // integer, fp16-exact
        __half hs = __float2half_rn(s);
        __half2 c2 = __halves2half2(hc, hc);
        __half2 s2 = __halves2half2(hs, hs);
        g_cz[idx] = make_uint2(*reinterpret_cast<uint32_t*>(&c2),
                               *reinterpret_cast<uint32_t*>(&s2));
    }
}

// ---------------------------------------------------------------------------
// Kernel 2: fused dequant + mma.sync fp16 GEMM.
// CTA 128x256, 8 warps (2x4, warp tile 64x64), BK=64 halves, 4-stage pipeline.
// A: cp.async from g_xh.  B: LDG packed int4 -> LOP3 dequant -> STS (fused).
// ---------------------------------------------------------------------------
constexpr int BM = 128, BN = 256, BK = 64;
constexpr int NIT = INF / BK;                 // 64
constexpr int TILE_A = BM * 128;              // 16384 B
constexpr int TILE_B = BN * 128;              // 32768 B
constexpr int STG = TILE_A + TILE_B;          // 49152 B
constexpr int SMEM_BYTES = 4 * STG;           // 196608 B
constexpr int NTHR = 256;

__global__ void __launch_bounds__(NTHR, 1) gemm_kernel(
        const int* __restrict__ wp, float* __restrict__ out) {
    extern __shared__ char smem[];
    const uint32_t sb = smem_u32(smem);
    const int tid = threadIdx.x;
    const int wid = tid >> 5;
    const int lid = tid & 31;
    const int wm = wid >> 2;                  // 0..1  (64 M-rows)
    const int wn = wid & 3;                   // 0..3  (64 N-rows)
    const int n0 = blockIdx.x * BN;
    const int m0 = blockIdx.y * BM;

    const char* gA = (const char*)g_xh + (size_t)m0 * (INF * 2);

    // shared per-thread addressing: row-block rowb, 16B-chunk cc
    const int rowb = tid >> 3;                // 0..31
    const int cc   = tid & 7;
    const uint32_t soff0 = (uint32_t)(rowb * 128 + ((cc ^ (rowb & 7)) << 4));
    const size_t   goffa0 = (size_t)rowb * (INF * 2) + (size_t)cc * 16;
    const int pb0  = ((n0 + rowb) << 9) + cc; // packed-int index base
    const int czb0 = (n0 + rowb) * 32;        // cz table base

    uint2 cz[8];
    uint32_t pk[8];

    auto loadA = [&](int kc) {
        uint32_t tb = sb + (kc & 3) * STG;
#pragma unroll
        for (int r = 0; r < 4; ++r)
            cp16(tb + soff0 + r * 4096, gA + goffa0 + (size_t)r * 262144
                                           + (size_t)kc * 128);
        asm volatile("cp.async.commit_group;" ::: "memory");
    };
    auto loadB = [&](int kc) {
        if ((kc & 1) == 0) {                  // new group (group = 2 chunks)
            int g = kc >> 1;
#pragma unroll
            for (int r = 0; r < 8; ++r) cz[r] = g_cz[czb0 + r * 1024 + g];
        }
#pragma unroll
        for (int r = 0; r < 8; ++r)
            pk[r] = (uint32_t)__ldg(wp + pb0 + r * 16384 + kc * 8);
    };
    auto storeB = [&](int kc) {
        uint32_t tb = sb + (kc & 3) * STG + TILE_A;
#pragma unroll
        for (int r = 0; r < 8; ++r) {
            uint32_t v = pk[r] ^ 0x88888888u;             // signed-nibble bias
            uint32_t u0 = ((v & 0xFu) | ((v & 0xF0u) << 12)) | 0x64006400u;
            uint32_t w1 = v >> 8;
            uint32_t u1 = ((w1 & 0xFu) | ((w1 & 0xF0u) << 12)) | 0x64006400u;
            uint32_t w2 = v >> 16;
            uint32_t u2 = ((w2 & 0xFu) | ((w2 & 0xF0u) << 12)) | 0x64006400u;
            uint32_t w3 = v >> 24;
            uint32_t u3 = ((w3 & 0xFu) | ((w3 & 0xF0u) << 12)) | 0x64006400u;
            __half2 nc = *reinterpret_cast<__half2*>(&cz[r].x);
            __half2 sh = *reinterpret_cast<__half2*>(&cz[r].y);
            __half2 h0 = __hmul2(__hadd2(*reinterpret_cast<__half2*>(&u0), nc), sh);
            __half2 h1 = __hmul2(__hadd2(*reinterpret_cast<__half2*>(&u1), nc), sh);
            __half2 h2 = __hmul2(__hadd2(*reinterpret_cast<__half2*>(&u2), nc), sh);
            __half2 h3 = __hmul2(__hadd2(*reinterpret_cast<__half2*>(&u3), nc), sh);
            asm volatile("st.shared.v4.b32 [%0], {%1, %2, %3, %4};"
                         :: "r"(tb + soff0 + r * 4096),
                            "r"(*reinterpret_cast<uint32_t*>(&h0)),
                            "r"(*reinterpret_cast<uint32_t*>(&h1)),
                            "r"(*reinterpret_cast<uint32_t*>(&h2)),
                            "r"(*reinterpret_cast<uint32_t*>(&h3))
                         : "memory");
        }
    };

    // ldmatrix addressing (mapping validated R3-R13)
    const int a_row7 = wm * 64 + (lid & 15);       // + i*16
    const int a_cb   = lid >> 4;
    const int b_lrow = (lid & 7) + ((lid >> 4) << 3);
    const int b_cb   = (lid >> 3) & 1;
    const int b_row0 = wn * 64 + b_lrow;           // + h*16

    float acc[4][8][4];
#pragma unroll
    for (int i = 0; i < 4; ++i)
#pragma unroll
        for (int j = 0; j < 8; ++j)
#pragma unroll
            for (int q = 0; q < 4; ++q) acc[i][j][q] = 0.f;

    // prologue: chunks 0..2
#pragma unroll
    for (int kc = 0; kc < 3; ++kc) {
        loadA(kc);
        loadB(kc);
        storeB(kc);
    }
    asm volatile("cp.async.wait_group 2;" ::: "memory");
    __syncthreads();

    for (int it = 0; it < NIT; ++it) {
        const uint32_t tb = sb + (it & 3) * STG;
        const bool more = (it + 3 < NIT);
        if (more) {                   // issue loads early; dequant after MMA
            loadA(it + 3);
            loadB(it + 3);
        }

#pragma unroll
        for (int ks = 0; ks < 4; ++ks) {           // 4 x k16 per 64-half chunk
            uint32_t a[4][4];
#pragma unroll
            for (int i = 0; i < 4; ++i) {
                int row = a_row7 + i * 16;
                uint32_t ad = tb + row * 128
                            + ((((ks << 1) + a_cb) ^ (row & 7)) << 4);
                asm volatile(
                    "ldmatrix.sync.aligned.m8n8.x4.shared.b16 {%0,%1,%2,%3}, [%4];"
                    : "=r"(a[i][0]), "=r"(a[i][1]), "=r"(a[i][2]), "=r"(a[i][3])
                    : "r"(ad));
            }
            uint32_t bfr[8][2];
#pragma unroll
            for (int h = 0; h < 4; ++h) {
                int row = b_row0 + h * 16;
                uint32_t bd = tb + TILE_A + row * 128
                            + ((((ks << 1) + b_cb) ^ (row & 7)) << 4);
                uint32_t r0, r1, r2, r3;
                asm volatile(
                    "ldmatrix.sync.aligned.m8n8.x4.shared.b16 {%0,%1,%2,%3}, [%4];"
                    : "=r"(r0), "=r"(r1), "=r"(r2), "=r"(r3) : "r"(bd));
                bfr[2 * h][0] = r0;     bfr[2 * h][1] = r1;
                bfr[2 * h + 1][0] = r2; bfr[2 * h + 1][1] = r3;
            }
#pragma unroll
            for (int i = 0; i < 4; ++i)
#pragma unroll
                for (int j = 0; j < 8; ++j)
                    asm volatile(
                        "mma.sync.aligned.m16n8k16.row.col.f32.f16.f16.f32 "
                        "{%0,%1,%2,%3},{%4,%5,%6,%7},{%8,%9},{%0,%1,%2,%3};"
                        : "+f"(acc[i][j][0]), "+f"(acc[i][j][1]),
                          "+f"(acc[i][j][2]), "+f"(acc[i][j][3])
                        : "r"(a[i][0]), "r"(a[i][1]), "r"(a[i][2]), "r"(a[i][3]),
                          "r"(bfr[j][0]), "r"(bfr[j][1]));
        }

        if (more) {
            storeB(it + 3);           // data arrived during MMA phase
            asm volatile("cp.async.wait_group 2;" ::: "memory");
        } else {
            asm volatile("cp.async.wait_group 0;" ::: "memory");
        }
        __syncthreads();
    }

    // epilogue
    const int mrow = m0 + wm * 64 + (lid >> 2);
    const int ncol = n0 + wn * 64 + ((lid & 3) << 1);
#pragma unroll
    for (int i = 0; i < 4; ++i) {
#pragma unroll
        for (int j = 0; j < 8; ++j) {
            float* p0 = out + (size_t)(mrow + i * 16) * OUTF + ncol + j * 8;
            float* p1 = out + (size_t)(mrow + i * 16 + 8) * OUTF + ncol + j * 8;
            *reinterpret_cast<float2*>(p0) = make_float2(acc[i][j][0], acc[i][j][1]);
            *reinterpret_cast<float2*>(p1) = make_float2(acc[i][j][2], acc[i][j][3]);
        }
    }
}

// ---------------------------------------------------------------------------
// launch
// ---------------------------------------------------------------------------
extern "C" void kernel_launch(void* const* d_in, const int* in_sizes, int n_in,
                              void* d_out, int out_size) {
    const float* x  = (const float*)d_in[0];
    const int*   wp = (const int*)d_in[1];
    const float* ws = (const float*)d_in[2];
    const int*   wz = (const int*)d_in[3];
    float* out = (float*)d_out;

    cudaFuncSetAttribute(gemm_kernel,
                         cudaFuncAttributeMaxDynamicSharedMemorySize, SMEM_BYTES);

    prep_kernel<<<4096 + 512, 256>>>(reinterpret_cast<const float4*>(x), ws, wz);
    gemm_kernel<<<dim3(OUTF / BN, MDIM / BM), NTHR, SMEM_BYTES>>>(wp, out);
}